// round 2
// baseline (speedup 1.0000x reference)
#include <cuda_runtime.h>
#include <cstdint>

#define N_USERS 100000
#define N_ITEMS 60000
#define N_NODES 160000
#define D 64
#define D2 32              // D in float2 units
#define NNZ 1280000
#define EPS 0.1f
#define SCAN_BS 1024
#define NB_SCAN ((N_NODES + SCAN_BS - 1) / SCAN_BS)   // 157

// ---------------- scratch (static device globals; no allocation) -------------
__device__ int   g_cnt[N_NODES];                 // zero-init; invariant: zero between calls
__device__ int   g_rowptr[N_NODES + 1];
__device__ int   g_cursor[N_NODES];
__device__ unsigned long long g_state[NB_SCAN];  // decoupled-lookback state
__device__ int2  g_edges[NNZ];                   // packed (col, val-bits)
__device__ float g_ego1[(size_t)N_NODES * D];    // output of layer 0
__device__ float g_ego2[(size_t)N_NODES * D];    // output of layer 1

// ---------------- histogram (block 0 also resets lookback state) -------------
__global__ void k_hist(const int* __restrict__ rows) {
    if (blockIdx.x == 0 && threadIdx.x < NB_SCAN) g_state[threadIdx.x] = 0ULL;
    int e = blockIdx.x * blockDim.x + threadIdx.x;
    if (e < NNZ) atomicAdd(&g_cnt[rows[e]], 1);
}

// ---------------- single-pass exclusive scan with decoupled lookback ---------
// Produces g_rowptr (exclusive prefix) + g_cursor copy, re-zeros g_cnt.
// Flags in bits[32..33]: 1 = aggregate, 2 = inclusive prefix.
__global__ void k_scan() {
    __shared__ int wsum[32];
    __shared__ int s_running;
    const int bid  = blockIdx.x;
    const int i    = bid * SCAN_BS + threadIdx.x;
    const int lane = threadIdx.x & 31;
    const int wid  = threadIdx.x >> 5;

    int v = (i < N_NODES) ? g_cnt[i] : 0;
    if (i < N_NODES) g_cnt[i] = 0;               // restore invariant for next call

    // block-wide inclusive scan
    int s = v;
    #pragma unroll
    for (int d = 1; d < 32; d <<= 1) {
        int t = __shfl_up_sync(0xffffffffu, s, d);
        if (lane >= d) s += t;
    }
    if (lane == 31) wsum[wid] = s;
    __syncthreads();
    if (wid == 0) {
        int ws = wsum[lane];
        #pragma unroll
        for (int d = 1; d < 32; d <<= 1) {
            int t = __shfl_up_sync(0xffffffffu, ws, d);
            if (lane >= d) ws += t;
        }
        wsum[lane] = ws;
    }
    __syncthreads();
    const int incl  = s + (wid ? wsum[wid - 1] : 0);
    const int total = wsum[31];

    // publish aggregate (block 0: directly the inclusive prefix)
    if (threadIdx.x == 0) {
        unsigned long long pk = ((bid == 0) ? (2ULL << 32) : (1ULL << 32))
                                | (unsigned)total;
        __threadfence();
        atomicExch(&g_state[bid], pk);
        if (bid == 0) { s_running = 0; g_rowptr[N_NODES] = NNZ; }
    }

    // warp-parallel lookback (warp 0)
    if (wid == 0 && bid > 0) {
        int running = 0;
        int pb = bid - 1;
        while (true) {
            int idx = pb - lane;
            unsigned long long st = 0ULL;
            if (idx >= 0) {
                do {
                    st = *(volatile unsigned long long*)&g_state[idx];
                } while ((st >> 32) == 0ULL);
            }
            unsigned pm = __ballot_sync(0xffffffffu, (idx >= 0) && ((st >> 32) == 2ULL));
            int val = (idx >= 0) ? (int)(st & 0xffffffffULL) : 0;
            if (pm) {
                int fp = __ffs(pm) - 1;                 // nearest block with PREFIX
                int contrib = (lane <= fp) ? val : 0;
                #pragma unroll
                for (int m = 16; m; m >>= 1) contrib += __shfl_xor_sync(0xffffffffu, contrib, m);
                running += contrib;
                break;
            } else {
                int contrib = val;
                #pragma unroll
                for (int m = 16; m; m >>= 1) contrib += __shfl_xor_sync(0xffffffffu, contrib, m);
                running += contrib;
                pb -= 32;
            }
        }
        if (lane == 0) {
            __threadfence();
            atomicExch(&g_state[bid], (2ULL << 32) | (unsigned)(total + running));
            s_running = running;
        }
    }
    __syncthreads();

    const int excl = incl - v + s_running;
    if (i < N_NODES) { g_rowptr[i] = excl; g_cursor[i] = excl; }
}

// ---------------- scatter COO -> CSR (packed edges) ---------------------------
__global__ void k_scatter(const int* __restrict__ rows,
                          const int* __restrict__ cols,
                          const float* __restrict__ vals) {
    int e = blockIdx.x * blockDim.x + threadIdx.x;
    if (e < NNZ) {
        int r = rows[e];
        int p = atomicAdd(&g_cursor[r], 1);
        g_edges[p] = make_int2(cols[e], __float_as_int(vals[e]));
    }
}

// ---------------- fused SpMM + noise-perturb + epilogue ----------------------
// One warp per output row; each lane owns 2 consecutive features (float2).
// x addressed via (xu, xi): layer 0 uses the two separate input tables; layers
// 1/2 set xi = xu + N_USERS*D2 so the select reconstructs a contiguous buffer.
template <int K>
__global__ void k_spmm(const float2* __restrict__ xu,
                       const float2* __restrict__ xi,
                       const float2* __restrict__ noise,   // offset to layer K
                       const float2* __restrict__ prevA,   // K==2: ego1
                       const float2* __restrict__ prevB,   // K==2: ego2
                       float2* __restrict__ yout,          // K==0/1
                       float2* __restrict__ out2)          // d_out as float2
{
    int gw   = (blockIdx.x * blockDim.x + threadIdx.x) >> 5;
    int lane = threadIdx.x & 31;
    if (gw >= N_NODES) return;
    int start = g_rowptr[gw];
    int end   = g_rowptr[gw + 1];

    float2 acc = make_float2(0.f, 0.f);
    for (int p = start; p < end; p += 32) {
        int cnt = min(32, end - p);
        int   c = 0;
        float v = 0.f;
        if (lane < cnt) {
            int2 e = __ldg(&g_edges[p + lane]);
            c = e.x;
            v = __int_as_float(e.y);
        }
        for (int base = 0; base < cnt; base += 8) {
            #pragma unroll
            for (int j = 0; j < 8; ++j) {
                int idx = base + j;
                if (idx < cnt) {
                    int   cc = __shfl_sync(0xffffffffu, c, idx);
                    float vv = __shfl_sync(0xffffffffu, v, idx);
                    const float2* xr = (cc < N_USERS)
                        ? (xu + (size_t)cc * D2)
                        : (xi + (size_t)(cc - N_USERS) * D2);
                    float2 t = __ldg(xr + lane);
                    acc.x = fmaf(vv, t.x, acc.x);
                    acc.y = fmaf(vv, t.y, acc.y);
                }
            }
        }
    }

    // noise perturbation: ego += sign(ego) * (n / max(||n||, 1e-12)) * EPS
    size_t off = (size_t)gw * D2 + lane;
    float2 nk = __ldcs(noise + off);              // streaming: don't pollute L2
    float ss = nk.x * nk.x + nk.y * nk.y;
    #pragma unroll
    for (int m = 16; m; m >>= 1) ss += __shfl_xor_sync(0xffffffffu, ss, m);
    float inv = EPS / fmaxf(sqrtf(ss), 1e-12f);
    float sx = (acc.x > 0.f) ? 1.f : ((acc.x < 0.f) ? -1.f : 0.f);
    float sy = (acc.y > 0.f) ? 1.f : ((acc.y < 0.f) ? -1.f : 0.f);
    acc.x += sx * nk.x * inv;
    acc.y += sy * nk.y * inv;

    if (K == 0) {
        yout[off] = acc;                                    // ego1 (reused: keep cached)
        __stcs(out2 + (size_t)N_NODES * D2 + off, acc);     // CL region: stream out
    } else if (K == 1) {
        yout[off] = acc;                                    // ego2 (gathered next layer)
    } else {
        float2 a = __ldcs(prevA + off);                     // ego1: last use, stream
        float2 b = __ldg(prevB + off);                      // ego2: L2-hot
        const float third = 1.f / 3.f;
        float2 f = make_float2((a.x + b.x + acc.x) * third,
                               (a.y + b.y + acc.y) * third);
        __stcs(out2 + off, f);                              // final region: stream out
    }
}

// ---------------- launch ------------------------------------------------------
extern "C" void kernel_launch(void* const* d_in, const int* in_sizes, int n_in,
                              void* d_out, int out_size) {
    const float* user_emb = (const float*)d_in[0];
    const float* item_emb = (const float*)d_in[1];
    const float* adj_vals = (const float*)d_in[2];
    const float* noise    = (const float*)d_in[3];
    const int*   adj_rows = (const int*)d_in[4];
    const int*   adj_cols = (const int*)d_in[5];
    float2* out2 = (float2*)d_out;

    // --- build CSR from COO (3 kernels: hist, single-pass scan, scatter) ---
    k_hist<<<NNZ / 256, 256>>>(adj_rows);
    k_scan<<<NB_SCAN, SCAN_BS>>>();
    k_scatter<<<NNZ / 256, 256>>>(adj_rows, adj_cols, adj_vals);

    static float2* ego1 = nullptr;
    static float2* ego2 = nullptr;
    if (!ego1) {
        void* p;
        cudaGetSymbolAddress(&p, g_ego1); ego1 = (float2*)p;
        cudaGetSymbolAddress(&p, g_ego2); ego2 = (float2*)p;
    }

    const float2* noise2 = (const float2*)noise;
    const int threads = 256;
    const int blocks  = (N_NODES * 32 + threads - 1) / threads;   // 20000

    // layer 0: x = concat(user_emb, item_emb) via two base pointers
    k_spmm<0><<<blocks, threads>>>((const float2*)user_emb,
                                   (const float2*)item_emb,
                                   noise2,
                                   nullptr, nullptr, ego1, out2);
    // layer 1: x = ego1 (contiguous -> xi = xu + N_USERS*D2)
    k_spmm<1><<<blocks, threads>>>((const float2*)ego1,
                                   (const float2*)ego1 + (size_t)N_USERS * D2,
                                   noise2 + (size_t)1 * N_NODES * D2,
                                   nullptr, nullptr, ego2, out2);
    // layer 2: x = ego2; epilogue writes final = (ego1+ego2+ego3)/3
    k_spmm<2><<<blocks, threads>>>((const float2*)ego2,
                                   (const float2*)ego2 + (size_t)N_USERS * D2,
                                   noise2 + (size_t)2 * N_NODES * D2,
                                   (const float2*)ego1, (const float2*)ego2,
                                   nullptr, out2);
}